// round 9
// baseline (speedup 1.0000x reference)
#include <cuda_runtime.h>

// StochasticPool2d: 2x2 stride-2 gumbel-max stochastic pooling.  FINAL.
// x:      [B=32, C=64, H=224, W=224] fp32
// gumbel: [B,C,112,112,4] fp32
// out:    [B,C,112,112] fp32
//
// HBM-roofline one-shot streaming kernel: 2 output pixels/thread, block=256
// (optimum of the 128/256/512 sweep), 31 regs, ~80% occupancy, ~90% DRAM
// busy / 7.2 TB/s. Traffic is provably minimal (925 MB, single-touch).
// 8-round exploration: more px/thread, .cs hints, persistent grid, and other
// block sizes all measured equal-or-worse; this config is the measured
// ceiling (run-to-run noise ±1 us).
//
// Index math minimized: with pair index t,
//   out offset = 2*t,  gum offset = 8*t,  x offset = 8*t - 4*(t % 56).
// Grid divides N_PAIRS exactly — no tail predicate.

static constexpr int Wc = 224;
static constexpr int NW = 112;
static constexpr int N_OUT   = 32 * 64 * 112 * NW;  // 25,690,112
static constexpr int N_PAIRS = N_OUT / 2;           // 12,845,056
static constexpr int PPR     = NW / 2;              // 56 pairs per output row

__device__ __forceinline__ float pick4(float v0, float v1, float v2, float v3,
                                       float g0, float g1, float g2, float g3)
{
    // score_k = (v_k > 0 ? log(v_k) : log(1)=0) + gumbel_k ; first-max argmax
    float s0 = (v0 > 0.0f ? __logf(v0) : 0.0f) + g0;
    float s1 = (v1 > 0.0f ? __logf(v1) : 0.0f) + g1;
    float s2 = (v2 > 0.0f ? __logf(v2) : 0.0f) + g2;
    float s3 = (v3 > 0.0f ? __logf(v3) : 0.0f) + g3;

    float best_s = s0;
    float best_v = v0;
    if (s1 > best_s) { best_s = s1; best_v = v1; }
    if (s2 > best_s) { best_s = s2; best_v = v2; }
    if (s3 > best_s) { best_s = s3; best_v = v3; }
    return best_v;
}

__global__ void __launch_bounds__(256)
stochastic_pool2d_kernel(const float* __restrict__ x,
                         const float* __restrict__ gum,
                         float* __restrict__ out)
{
    int t = blockIdx.x * blockDim.x + threadIdx.x;   // pair index, always < N_PAIRS

    // gumbel address is linear in t — loads issue immediately.
    const float* gp = gum + (size_t)t * 8;
    float4 g0 = *reinterpret_cast<const float4*>(gp);
    float4 g1 = *reinterpret_cast<const float4*>(gp + 4);

    // x: offset = 8t - 4*(t % 56); second window row is +Wc.
    int jp = t % PPR;
    const float* xrow = x + ((size_t)t * 8 - (size_t)(4 * jp));
    float4 x0 = *reinterpret_cast<const float4*>(xrow);        // row 2i
    float4 x1 = *reinterpret_cast<const float4*>(xrow + Wc);   // row 2i+1

    // Window flatten order k = di*2 + dj (row-major within 2x2).
    float2 o;
    o.x = pick4(x0.x, x0.y, x1.x, x1.y, g0.x, g0.y, g0.z, g0.w); // pixel 2t
    o.y = pick4(x0.z, x0.w, x1.z, x1.w, g1.x, g1.y, g1.z, g1.w); // pixel 2t+1

    *reinterpret_cast<float2*>(out + (size_t)t * 2) = o;
}

extern "C" void kernel_launch(void* const* d_in, const int* in_sizes, int n_in,
                              void* d_out, int out_size)
{
    const float* x   = (const float*)d_in[0];
    const float* gum = (const float*)d_in[1];
    float* out = (float*)d_out;

    const int threads = 256;
    const int blocks  = N_PAIRS / threads;   // 50,176 exactly
    stochastic_pool2d_kernel<<<blocks, threads>>>(x, gum, out);
}

// round 10
// speedup vs baseline: 1.0148x; 1.0148x over previous
#include <cuda_runtime.h>

// StochasticPool2d: 2x2 stride-2 gumbel-max stochastic pooling.  FINAL.
// x:      [B=32, C=64, H=224, W=224] fp32
// gumbel: [B,C,112,112,4] fp32
// out:    [B,C,112,112] fp32
//
// HBM-roofline one-shot streaming kernel: 2 output pixels/thread, block=256,
// 31 regs, ~80% occupancy, ~90% DRAM busy / 7.1-7.2 TB/s on a provably
// minimal 925 MB single-touch stream. 9-round exploration established this
// as the measured ceiling: 4px/thread (occ loss), .cs hints, persistent
// grid (MLP collapse), block=128/512 all equal-or-worse; identical-binary
// reruns span +/-1 us, bracketing all remaining variants.
//
// Index math minimized: with pair index t,
//   out offset = 2*t,  gum offset = 8*t,  x offset = 8*t - 4*(t % 56).
// Grid divides N_PAIRS exactly — no tail predicate.

static constexpr int Wc = 224;
static constexpr int NW = 112;
static constexpr int N_OUT   = 32 * 64 * 112 * NW;  // 25,690,112
static constexpr int N_PAIRS = N_OUT / 2;           // 12,845,056
static constexpr int PPR     = NW / 2;              // 56 pairs per output row

__device__ __forceinline__ float pick4(float v0, float v1, float v2, float v3,
                                       float g0, float g1, float g2, float g3)
{
    // score_k = (v_k > 0 ? log(v_k) : log(1)=0) + gumbel_k ; first-max argmax
    float s0 = (v0 > 0.0f ? __logf(v0) : 0.0f) + g0;
    float s1 = (v1 > 0.0f ? __logf(v1) : 0.0f) + g1;
    float s2 = (v2 > 0.0f ? __logf(v2) : 0.0f) + g2;
    float s3 = (v3 > 0.0f ? __logf(v3) : 0.0f) + g3;

    float best_s = s0;
    float best_v = v0;
    if (s1 > best_s) { best_s = s1; best_v = v1; }
    if (s2 > best_s) { best_s = s2; best_v = v2; }
    if (s3 > best_s) { best_s = s3; best_v = v3; }
    return best_v;
}

__global__ void __launch_bounds__(256)
stochastic_pool2d_kernel(const float* __restrict__ x,
                         const float* __restrict__ gum,
                         float* __restrict__ out)
{
    int t = blockIdx.x * blockDim.x + threadIdx.x;   // pair index, always < N_PAIRS

    // gumbel address is linear in t — loads issue immediately.
    const float* gp = gum + (size_t)t * 8;
    float4 g0 = *reinterpret_cast<const float4*>(gp);
    float4 g1 = *reinterpret_cast<const float4*>(gp + 4);

    // x: offset = 8t - 4*(t % 56); second window row is +Wc.
    int jp = t % PPR;
    const float* xrow = x + ((size_t)t * 8 - (size_t)(4 * jp));
    float4 x0 = *reinterpret_cast<const float4*>(xrow);        // row 2i
    float4 x1 = *reinterpret_cast<const float4*>(xrow + Wc);   // row 2i+1

    // Window flatten order k = di*2 + dj (row-major within 2x2).
    float2 o;
    o.x = pick4(x0.x, x0.y, x1.x, x1.y, g0.x, g0.y, g0.z, g0.w); // pixel 2t
    o.y = pick4(x0.z, x0.w, x1.z, x1.w, g1.x, g1.y, g1.z, g1.w); // pixel 2t+1

    *reinterpret_cast<float2*>(out + (size_t)t * 2) = o;
}

extern "C" void kernel_launch(void* const* d_in, const int* in_sizes, int n_in,
                              void* d_out, int out_size)
{
    const float* x   = (const float*)d_in[0];
    const float* gum = (const float*)d_in[1];
    float* out = (float*)d_out;

    const int threads = 256;
    const int blocks  = N_PAIRS / threads;   // 50,176 exactly
    stochastic_pool2d_kernel<<<blocks, threads>>>(x, gum, out);
}